// round 16
// baseline (speedup 1.0000x reference)
#include <cuda_runtime.h>
#include <math.h>

#define BB   32
#define SEQ  64
#define EMB  512
#define HID  512
#define NREG 196
#define VOC  32000
#define SQRTE 22.62741699796952f
#define NCTA 148
#define NCTA2 296
#define RTHREADS 384
#define RWARPS 12

// ---------------- device scratch (static; no runtime alloc) ----------------
__device__ float    g_emb[BB * SEQ * EMB];       // 4 MB  [m][e], m = b*64+t
__device__ float    g_h[BB * HID];
__device__ float    g_c[BB * HID];
__device__ float    g_sc[BB * NREG];
__device__ float    g_ctx[BB * EMB];
__device__ float    g_xe[BB * SEQ * EMB];        // 4 MB  emb-half of reshape (+rb)
__device__ unsigned g_Ht[BB * SEQ * HID];        // 4 MB  tf32 bits of H, row m=b*64+t
__device__ float    g_rWT[EMB * EMB];            // 1 MB  rW[:, :512] transposed
__device__ float    g_M[4 * HID * EMB];          // 4 MB  M = Wih @ rW1
__device__ float    g_pre2T[SEQ * 4 * HID * BB]; // 16 MB pre2T[t][r][b]
__device__ unsigned g_oWt[VOC * EMB];            // 65.5 MB tf32 bits of out_W
__device__ unsigned g_arrive;                    // k_rec barrier
__device__ unsigned g_arrive2;                   // k_hoist barrier

// ---------------- helpers ----------------
__device__ __forceinline__ float allsum(float v) {
    #pragma unroll
    for (int o = 16; o > 0; o >>= 1) v += __shfl_xor_sync(0xffffffffu, v, o);
    return v;
}
__device__ __forceinline__ float allmax(float v) {
    #pragma unroll
    for (int o = 16; o > 0; o >>= 1) v = fmaxf(v, __shfl_xor_sync(0xffffffffu, v, o));
    return v;
}
// packed dual-FMA (FFMA2) — only reachable via PTX fma.rn.f32x2 on sm_10x
__device__ __forceinline__ void ffma2(float2& d, const float2& a, const float2& b) {
    asm("fma.rn.f32x2 %0, %1, %2, %0;"
        : "+l"(*reinterpret_cast<unsigned long long*>(&d))
        : "l"(*reinterpret_cast<const unsigned long long*>(&a)),
          "l"(*reinterpret_cast<const unsigned long long*>(&b)));
}
__device__ __forceinline__ void dotacc(float2& acc, const float4& w, const float4& v) {
    float2 a0 = make_float2(w.x, w.y), b0 = make_float2(v.x, v.y);
    ffma2(acc, a0, b0);
    float2 a1 = make_float2(w.z, w.w), b1 = make_float2(v.z, v.w);
    ffma2(acc, a1, b1);
}
__device__ __forceinline__ unsigned f2tf32(float x) {
    unsigned u;
    asm("cvt.rna.tf32.f32 %0, %1;" : "=r"(u) : "f"(x));
    return u;
}
__device__ __forceinline__ void mma_tf32(float* d, const unsigned* a, const unsigned* b) {
    asm("mma.sync.aligned.m16n8k8.row.col.f32.tf32.tf32.f32 "
        "{%0,%1,%2,%3}, {%4,%5,%6,%7}, {%8,%9}, {%0,%1,%2,%3};"
        : "+f"(d[0]), "+f"(d[1]), "+f"(d[2]), "+f"(d[3])
        : "r"(a[0]), "r"(a[1]), "r"(a[2]), "r"(a[3]), "r"(b[0]), "r"(b[1]));
}
__device__ __forceinline__ unsigned smem_u32(const void* p) {
    unsigned a;
    asm("{ .reg .u64 t; cvta.to.shared.u64 t, %1; cvt.u32.u64 %0, t; }"
        : "=r"(a) : "l"(p));
    return a;
}
__device__ __forceinline__ void cpasync16(unsigned s, const void* g) {
    asm volatile("cp.async.cg.shared.global [%0], [%1], 16;"
                 :: "r"(s), "l"((unsigned long long)__cvta_generic_to_global(g)));
}

// grid-wide software barriers (release/acquire)
__device__ __forceinline__ void gbar_on(unsigned* ctr, unsigned& ep, unsigned inc) {
    ep += inc;
    __syncthreads();
    if (threadIdx.x == 0) {
        asm volatile("red.release.gpu.add.u32 [%0], %1;"
                     :: "l"(ctr), "r"(1u) : "memory");
        unsigned v;
        do {
            asm volatile("ld.acquire.gpu.u32 %0, [%1];"
                         : "=r"(v) : "l"(ctr) : "memory");
        } while (v < ep);
    }
    __syncthreads();
}
__device__ __forceinline__ void gbar(unsigned& ep) { gbar_on(&g_arrive, ep, NCTA); }

// ---------------- fused one-time prep (launch 0) ----------------------------
__global__ void k_prep(const int* __restrict__ caps, const float* __restrict__ embW,
                       const float* __restrict__ rW, const float* __restrict__ F,
                       const float* __restrict__ hW, const float* __restrict__ hb,
                       const float* __restrict__ cW, const float* __restrict__ cb,
                       const float* __restrict__ oW) {
    __shared__ float tile[32][33];
    __shared__ float sfm[512];
    int bid = blockIdx.x, tid = threadIdx.x;
    if (bid == 0 && tid == 0) { g_arrive = 0; g_arrive2 = 0; }   // barrier resets
    if (bid < 4096) {                                     // embeddings
        int idx = bid * 256 + tid;
        int bt = idx >> 9, e = idx & 511;
        g_emb[idx] = embW[caps[bt] * 512 + e] * SQRTE;
    } else if (bid < 4352) {                              // rWT
        int tI = bid - 4096;
        int bk = (tI & 15) * 32, bj = (tI >> 4) * 32;
        int tx = tid & 31, ty0 = tid >> 5;
        #pragma unroll
        for (int i = 0; i < 4; i++) {
            int ty = ty0 + i * 8;
            tile[ty][tx] = rW[(size_t)(bj + ty) * 1024 + bk + tx];
        }
        __syncthreads();
        #pragma unroll
        for (int i = 0; i < 4; i++) {
            int ty = ty0 + i * 8;
            g_rWT[(size_t)(bk + ty) * 512 + bj + tx] = tile[tx][ty];
        }
    } else if (bid < 4416) {                              // h0/c0 init
        int bid2 = bid - 4352;
        int which = bid2 >> 5, b = bid2 & 31;
        #pragma unroll
        for (int rep = 0; rep < 2; rep++) {
            int e = tid + rep * 256;
            const float* p = F + (size_t)b * NREG * EMB + e;
            float s0 = 0.f, s1 = 0.f;
            #pragma unroll 2
            for (int n = 0; n < NREG; n += 2) {
                s0 += p[(size_t)n * EMB];
                if (n + 1 < NREG) s1 += p[(size_t)(n + 1) * EMB];
            }
            sfm[e] = (s0 + s1) * (1.0f / NREG);
        }
        __syncthreads();
        int lane = tid & 31, w = tid >> 5;
        const float* Wm = which ? cW : hW;
        const float* bv = which ? cb : hb;
        const float4* fp = (const float4*)sfm;
        for (int jj = 0; jj < 64; jj++) {
            int j = w * 64 + jj;
            const float4* Wp = (const float4*)(Wm + (size_t)j * EMB);
            float s = 0.f;
            #pragma unroll
            for (int i = 0; i < 4; i++) {
                int id = lane + i * 32;
                float4 a = Wp[id], x = fp[id];
                s += a.x * x.x + a.y * x.y + a.z * x.z + a.w * x.w;
            }
            s = allsum(s);
            if (lane == 0) {
                if (which) g_c[b * HID + j] = s + bv[j];
                else       g_h[b * HID + j] = s + bv[j];
            }
        }
    } else {                                              // out_W -> tf32
        int idx = (bid - 4416) * 256 + tid;
        float4 v = ((const float4*)oW)[idx];
        uint4 u;
        u.x = f2tf32(v.x); u.y = f2tf32(v.y); u.z = f2tf32(v.z); u.w = f2tf32(v.w);
        ((uint4*)g_oWt)[idx] = u;
    }
}

// ---------------- fused hoists (launch 1): xe + M, barrier, pre2T ------------
// 296 CTAs (2/SM, co-resident) x 256 thr. 128x64 FFMA2 tiles.
struct SmemHoist { float2 As2[16 * 129]; float Bs[16 * 66]; };

__device__ void hoist_tile(SmemHoist& sm,
                           const float* __restrict__ A,
                           const float* __restrict__ Bm, int ldb,
                           const float* __restrict__ bias,
                           float* __restrict__ C, int transout,
                           int vt, int mt) {
    int tid = threadIdx.x;
    int tx = tid & 15, ty = tid >> 4;
    float2 acc[8][2];
    #pragma unroll
    for (int i = 0; i < 8; i++)
        #pragma unroll
        for (int q = 0; q < 2; q++) acc[i][q] = make_float2(0.f, 0.f);

    for (int kc = 0; kc < 32; kc++) {
        __syncthreads();
        #pragma unroll
        for (int i = 0; i < 2; i++) {
            int f4 = tid + i * 256;
            int m = f4 >> 2, kk = f4 & 3;
            float4 a = *(const float4*)(A + (size_t)(mt + m) * 512 + kc * 16 + kk * 4);
            int kb = kk * 4;
            sm.As2[(kb + 0) * 129 + m] = make_float2(a.x, a.x);
            sm.As2[(kb + 1) * 129 + m] = make_float2(a.y, a.y);
            sm.As2[(kb + 2) * 129 + m] = make_float2(a.z, a.z);
            sm.As2[(kb + 3) * 129 + m] = make_float2(a.w, a.w);
        }
        {
            int m = tid >> 2, kk = tid & 3;
            float4 bv = *(const float4*)(Bm + (size_t)(vt + m) * ldb + kc * 16 + kk * 4);
            int kb = kk * 4;
            sm.Bs[(kb + 0) * 66 + m] = bv.x;
            sm.Bs[(kb + 1) * 66 + m] = bv.y;
            sm.Bs[(kb + 2) * 66 + m] = bv.z;
            sm.Bs[(kb + 3) * 66 + m] = bv.w;
        }
        __syncthreads();
        #pragma unroll
        for (int k = 0; k < 16; k++) {
            float2 b2[2];
            #pragma unroll
            for (int q = 0; q < 2; q++)
                b2[q] = *(const float2*)&sm.Bs[k * 66 + 2 * tx + 32 * q];
            #pragma unroll
            for (int i = 0; i < 8; i++) {
                float2 a2 = sm.As2[k * 129 + ty * 8 + i];
                #pragma unroll
                for (int q = 0; q < 2; q++) ffma2(acc[i][q], a2, b2[q]);
            }
        }
    }
    #pragma unroll
    for (int q = 0; q < 2; q++) {
        int v = vt + 2 * tx + 32 * q;
        float2 bb = bias ? *(const float2*)(bias + v) : make_float2(0.f, 0.f);
        #pragma unroll
        for (int i = 0; i < 8; i++) {
            int m = mt + ty * 8 + i;
            float2 r = make_float2(acc[i][q].x + bb.x, acc[i][q].y + bb.y);
            if (!transout) {
                *(float2*)(C + (size_t)m * 512 + v) = r;
            } else {
                size_t base = ((size_t)((m & 63) * 2048 + v)) * 32 + (m >> 6);
                C[base]      = r.x;
                C[base + 32] = r.y;
            }
        }
    }
}

__global__ void __launch_bounds__(256)
k_hoist(const float* __restrict__ rW, const float* __restrict__ rb,
        const float* __restrict__ Wih) {
    __shared__ SmemHoist sm;
    unsigned ep2 = 0;
    // phase 1: xe (z=0, 128 tiles) + M (z=1, 128 tiles)
    for (int blk = blockIdx.x; blk < 256; blk += NCTA2) {
        int z = blk >> 7, r = blk & 127;
        int vt = (r & 7) * 64, mt = (r >> 3) * 128;
        if (z == 0) hoist_tile(sm, g_emb, rW + 512, 1024, rb, g_xe, 0, vt, mt);
        else        hoist_tile(sm, Wih, g_rWT, 512, (const float*)0, g_M, 0, vt, mt);
    }
    gbar_on(&g_arrive2, ep2, NCTA2);
    // phase 2: pre2T = xe @ Wih^T (512 tiles, transposed output)
    for (int blk = blockIdx.x; blk < 512; blk += NCTA2) {
        int vt = (blk & 31) * 64, mt = (blk >> 5) * 128;
        hoist_tile(sm, g_xe, Wih, 512, (const float*)0, g_pre2T, 1, vt, mt);
    }
}

// ---------------- persistent fused recurrence (launch 2, unchanged) ----------
__global__ void __launch_bounds__(RTHREADS, 1)
k_rec(const float* __restrict__ F, const float* __restrict__ Whh,
      const float* __restrict__ bih, const float* __restrict__ bhh) {
    extern __shared__ float4 smem4[];
    float4* act4  = smem4;
    float*  ws    = (float*)(smem4 + 8448);
    float*  abuf  = ws + 16384;
    float*  redC2 = abuf + 2688;
    float*  redB  = redC2 + 4096;
    const int tid = threadIdx.x, lane = tid & 31, w = tid >> 5;
    const int cta = blockIdx.x;
    unsigned ep = 0;

    const int u   = w & 3;
    const int nt3 = w >> 2;
    const int q   = cta + NCTA * u;
    const bool uvalid = (q < 512);

    if (w < 8 && uvalid) {
        const int kh = w >> 2;
        const float* src = kh ? Whh : g_M;
        #pragma unroll
        for (int g = 0; g < 4; g++) {
            const float* rp = src + (size_t)(q + g * 512) * 512;
            float* dst = ws + u * 4096 + kh * 2048 + g * 512;
            for (int j = lane; j < 512; j += 32) dst[j] = rp[j];
        }
    }
    float c_l = 0.f;
    float biasq[4] = {0.f, 0.f, 0.f, 0.f};
    if (uvalid && w < 4) {
        c_l = __ldcg(&g_c[lane * 512 + q]);
        #pragma unroll
        for (int g = 0; g < 4; g++) biasq[g] = bih[q + g * 512] + bhh[q + g * 512];
    }
    __syncthreads();

    const float4* F4 = (const float4*)F;
    const int gw = cta * RWARPS + w;

    for (int t = 0; t < SEQ; t++) {
        float pre[4];
        if (w < 4 && uvalid) {
            size_t pb = ((size_t)(t * 2048 + q)) * 32 + lane;
            #pragma unroll
            for (int g = 0; g < 4; g++) pre[g] = __ldg(&g_pre2T[pb + (size_t)g * 16384]);
        }
        // ======== Phase A ========
        {
            const float4* hg = (const float4*)g_h;
            for (int i = tid; i < 4096; i += RTHREADS) {
                float4 v = __ldcg(hg + i);
                act4[(i & 127) * 33 + (i >> 7)] = v;
            }
            __syncthreads();
            #pragma unroll
            for (int p = 0; p < 2; p++) {
                int d0 = gw + p * 3552;
                int d1 = d0 + 1776;
                bool v1 = (d1 < BB * NREG);
                int b0 = d0 / NREG;
                int b1 = v1 ? (d1 / NREG) : b0;
                const float4* fr0 = F4 + (size_t)d0 * 128;
                const float4* fr1 = F4 + (size_t)(v1 ? d1 : d0) * 128;
                float2 a0 = make_float2(0.f, 0.f), a1 = make_float2(0.f, 0.f);
                #pragma unroll
                for (int i = 0; i < 4; i++) {
                    int id = lane + 32 * i;
                    dotacc(a0, fr0[id], act4[id * 33 + b0]);
                    dotacc(a1, fr1[id], act4[id * 33 + b1]);
                }
                float s0 = a0.x + a0.y, s1 = a1.x + a1.y;
                #pragma unroll
                for (int o = 16; o > 0; o >>= 1) {
                    s0 += __shfl_xor_sync(0xffffffffu, s0, o);
                    s1 += __shfl_xor_sync(0xffffffffu, s1, o);
                }
                if (lane == 0) {
                    g_sc[d0] = s0;
                    if (v1) g_sc[d1] = s1;
                }
            }
        }
        gbar(ep);
        // ======== Phase B ========
        {
            float csum = 0.f;
            int b = 0, ec = 0;
            if (uvalid) {
                b = q >> 4; ec = q & 15;
                float ev[7];
                float mx = -3.4e38f;
                #pragma unroll
                for (int j = 0; j < 7; j++) {
                    int n = lane + j * 32;
                    float s = (n < NREG) ? __ldcg(&g_sc[b * NREG + n]) : -3.4e38f;
                    ev[j] = s;
                    mx = fmaxf(mx, s);
                }
                mx = allmax(mx);
                float sum = 0.f;
                #pragma unroll
                for (int j = 0; j < 7; j++) {
                    int n = lane + j * 32;
                    float e = (n < NREG) ? expf(ev[j] - mx) : 0.f;
                    ev[j] = e;
                    sum += e;
                }
                sum = allsum(sum);
                float inv = 1.f / sum;
                float* ab = abuf + w * 224;
                #pragma unroll
                for (int j = 0; j < 7; j++) {
                    int n = lane + j * 32;
                    if (n < NREG) ab[n] = ev[j] * inv;
                }
                __syncwarp();
                const float* fp = F + (size_t)b * NREG * EMB + ec * 32 + lane;
                int n0 = nt3 * 65;
                int n1 = (nt3 == 2) ? 196 : (n0 + 65);
                float a8[8];
                #pragma unroll
                for (int j = 0; j < 8; j++) a8[j] = 0.f;
                int n = n0;
                for (; n + 8 <= n1; n += 8) {
                    #pragma unroll
                    for (int j = 0; j < 8; j++)
                        a8[j] = fmaf(ab[n + j], fp[(size_t)(n + j) * 512], a8[j]);
                }
                for (; n < n1; n++) a8[0] = fmaf(ab[n], fp[(size_t)n * 512], a8[0]);
                csum = ((a8[0] + a8[1]) + (a8[2] + a8[3]))
                     + ((a8[4] + a8[5]) + (a8[6] + a8[7]));
                if (nt3) redB[u * 64 + (nt3 - 1) * 32 + lane] = csum;
            }
            __syncthreads();
            if (uvalid && nt3 == 0)
                g_ctx[b * 512 + ec * 32 + lane] =
                    csum + redB[u * 64 + lane] + redB[u * 64 + 32 + lane];
        }
        gbar(ep);
        // ======== Phase C ========
        {
            const float4* cg = (const float4*)g_ctx;
            for (int i = tid; i < 4096; i += RTHREADS) {
                float4 v = __ldcg(cg + i);
                act4[(128 + (i & 127)) * 33 + (i >> 7)] = v;
            }
            __syncthreads();
            if (w < 8) {
                const int side = w >> 2;
                const int qt = w & 3;
                const int baseRow = side * 128 + qt * 32;
                const int srcOff = side ? 0 : 2048;
                float2 pacc[4][4];
                #pragma unroll
                for (int uu = 0; uu < 4; uu++)
                    #pragma unroll
                    for (int g = 0; g < 4; g++) pacc[uu][g] = make_float2(0.f, 0.f);
                const float4* actp = act4 + (size_t)baseRow * 33 + lane;
                #pragma unroll 2
                for (int k4l = 0; k4l < 32; k4l++) {
                    float4 x = actp[k4l * 33];
                    #pragma unroll
                    for (int uu = 0; uu < 4; uu++) {
                        const float4* wp = (const float4*)(ws + uu * 4096 + srcOff)
                                         + qt * 32 + k4l;
                        #pragma unroll
                        for (int g = 0; g < 4; g++) {
                            float4 wg = wp[g * 128];
                            ffma2(pacc[uu][g], make_float2(wg.x, wg.y),
                                               make_float2(x.x, x.y));
                            ffma2(pacc[uu][g], make_float2(wg.z, wg.w),
                                               make_float2(x.z, x.w));
                        }
                    }
                }
                float* rC = redC2 + w * 512;
                #pragma unroll
                for (int uu = 0; uu < 4; uu++)
                    #pragma unroll
                    for (int g = 0; g < 4; g++)
                        rC[(uu * 4 + g) * 32 + lane] = pacc[uu][g].x + pacc[uu][g].y;
            }
            __syncthreads();
            if (w < 4 && uvalid) {
                float gate[4];
                #pragma unroll
                for (int g = 0; g < 4; g++) {
                    float s = 0.f;
                    #pragma unroll
                    for (int j = 0; j < 8; j++)
                        s += redC2[j * 512 + (w * 4 + g) * 32 + lane];
                    gate[g] = s + pre[g] + biasq[g];
                }
                float si = 1.f / (1.f + expf(-gate[0]));
                float sf = 1.f / (1.f + expf(-gate[1]));
                float so = 1.f / (1.f + expf(-gate[3]));
                c_l = sf * c_l + si * tanhf(gate[2]);
                float h2v = so * tanhf(c_l);
                g_h[lane * 512 + q] = h2v;
                g_Ht[(size_t)((lane << 6) + t) * 512 + q] = f2tf32(h2v);
            }
        }
        gbar(ep);
    }
}

// ---------------- tf32 tensor-core output GEMM (launch 3 — ncu slot) ---------
// 256x128 tiles, 3-stage cp.async pipeline, ONE __syncthreads per k-iter,
// streaming output stores. dyn smem: 3 x (256+128)x36x4 = 165888 B.
__global__ void __launch_bounds__(256, 1)
k_out_tc(const float* __restrict__ ob, float* __restrict__ out) {
    extern __shared__ unsigned sbuf[];
    int tid = threadIdx.x, lane = tid & 31, wid = tid >> 5;
    int wm = wid & 3, wn = wid >> 2;
    int mt = blockIdx.x * 256, vt = blockIdx.y * 128;
    unsigned sb = smem_u32(sbuf);

    float d[4][8][4];
    #pragma unroll
    for (int mi = 0; mi < 4; mi++)
        #pragma unroll
        for (int nj = 0; nj < 8; nj++)
            #pragma unroll
            for (int e = 0; e < 4; e++) d[mi][nj][e] = 0.f;

    int frow = tid >> 3;                 // 0..31
    int fcol = (tid & 7) * 4;            // 0..28
    #define FILL(ST, KC) do {                                                          \
        unsigned base = sb + (unsigned)(ST) * 55296u;                                  \
        _Pragma("unroll")                                                              \
        for (int i = 0; i < 8; i++) {                                                  \
            int row = frow + i * 32;                                                   \
            cpasync16(base + (unsigned)(row * 36 + fcol) * 4u,                         \
                      &g_Ht[(size_t)(mt + row) * 512 + (KC) * 32 + fcol]);             \
        }                                                                              \
        _Pragma("unroll")                                                              \
        for (int i = 0; i < 4; i++) {                                                  \
            int row = frow + i * 32;                                                   \
            cpasync16(base + 36864u + (unsigned)(row * 36 + fcol) * 4u,                \
                      &g_oWt[(size_t)(vt + row) * 512 + (KC) * 32 + fcol]);            \
        }                                                                              \
        asm volatile("cp.async.commit_group;" ::: "memory");                           \
    } while (0)

    FILL(0, 0);
    FILL(1, 1);
    #pragma unroll 4
    for (int kc = 0; kc < 16; kc++) {
        if (kc < 15) asm volatile("cp.async.wait_group 1;" ::: "memory");
        else         asm volatile("cp.async.wait_group 0;" ::: "memory");
        __syncthreads();
        int st = kc % 3;
        const unsigned* As  = sbuf + st * 13824;
        const unsigned* Bsm = As + 9216;
        int c = lane & 3, r = lane >> 2;
        #pragma unroll
        for (int k8 = 0; k8 < 4; k8++) {
            int k0 = k8 * 8;
            unsigned af[4][4];
            #pragma unroll
            for (int mi = 0; mi < 4; mi++) {
                int base = (wm * 64 + mi * 16 + r) * 36 + k0 + c;
                af[mi][0] = As[base];
                af[mi][1] = As[base + 8 * 36];
                af[mi][2] = As[base + 4];
                af[mi][3] = As[base + 8 * 36 + 4];
            }
            unsigned bf[8][2];
            #pragma unroll
            for (int nj = 0; nj < 8; nj++) {
                int base = (wn * 64 + nj * 8 + r) * 36 + k0 + c;
                bf[nj][0] = Bsm[base];
                bf[nj][1] = Bsm[base + 4];
            }
            #pragma unroll
            for (int mi = 0; mi < 4; mi++)
                #pragma unroll
                for (int nj = 0; nj < 8; nj++)
                    mma_tf32(d[mi][nj], af[mi], bf[nj]);
        }
        if (kc + 2 < 16) FILL((kc + 2) % 3, kc + 2);
    }
    #undef FILL
    int c = lane & 3, r = lane >> 2;
    #pragma unroll
    for (int mi = 0; mi < 4; mi++) {
        #pragma unroll
        for (int nj = 0; nj < 8; nj++) {
            int m0 = mt + wm * 64 + mi * 16 + r;
            int v0 = vt + wn * 64 + nj * 8 + 2 * c;
            float2 bb = *(const float2*)(ob + v0);
            float2 r0 = make_float2(d[mi][nj][0] + bb.x, d[mi][nj][1] + bb.y);
            float2 r1 = make_float2(d[mi][nj][2] + bb.x, d[mi][nj][3] + bb.y);
            __stcs((float2*)(out + (size_t)m0 * VOC + v0), r0);
            __stcs((float2*)(out + (size_t)(m0 + 8) * VOC + v0), r1);
        }
    }
}

// ---------------- launch ----------------
extern "C" void kernel_launch(void* const* d_in, const int* in_sizes, int n_in,
                              void* d_out, int out_size) {
    const float* features = (const float*)d_in[0];
    const int*   captions = (const int*)  d_in[1];
    const float* embW     = (const float*)d_in[2];
    const float* ihW      = (const float*)d_in[3];
    const float* ihb      = (const float*)d_in[4];
    const float* icW      = (const float*)d_in[5];
    const float* icb      = (const float*)d_in[6];
    const float* rW       = (const float*)d_in[7];
    const float* rb       = (const float*)d_in[8];
    const float* Wih      = (const float*)d_in[9];
    const float* Whh      = (const float*)d_in[10];
    const float* bih      = (const float*)d_in[11];
    const float* bhh      = (const float*)d_in[12];
    const float* oW       = (const float*)d_in[13];
    const float* ob       = (const float*)d_in[14];
    float* out = (float*)d_out;

    static int inited = 0;
    if (!inited) {
        cudaFuncSetAttribute(k_rec, cudaFuncAttributeMaxDynamicSharedMemorySize, 228864);
        cudaFuncSetAttribute(k_out_tc, cudaFuncAttributeMaxDynamicSharedMemorySize, 165888);
        inited = 1;
    }

    // launch 0: fused prep (embed + rW1 transpose + init + cvtW; resets barriers)
    k_prep<<<20416, 256>>>(captions, embW, rW, features, ihW, ihb, icW, icb, oW);
    // launch 1: fused hoists (xe + M, grid barrier, pre2T)
    k_hoist<<<NCTA2, 256>>>(rW, rb, Wih);
    // launch 2: recurrence (384 threads)
    k_rec<<<NCTA, RTHREADS, 228864>>>(features, Whh, bih, bhh);
    // launch 3: output projection (tf32 MMA, 3-stage pipeline)  <-- ncu slot
    k_out_tc<<<dim3(8, 250), 256, 165888>>>(ob, out);
}